// round 4
// baseline (speedup 1.0000x reference)
#include <cuda_runtime.h>

#define NCLS   10
#define NB     32
#define NBINS  (NB * NCLS)      // 320
#define NATOMS 16384
#define DIN    272
#define HID    64
#define NOUT   128
#define L0OUT  256
#define IN0    32
#define ATILE  64
#define BINCAP 512              // worst-case atoms per (b, cls) bin
#define GRID   NBINS            // one block per bin
#define NT     128
#define PADA   68

// static device scratch (module-init zero; replay-safe lifecycle below)
__device__ int      g_cnt[NBINS];
__device__ int      g_list[NBINS * BINCAP];
__device__ unsigned g_bar;      // monotonic epoch barrier counter

__device__ __forceinline__ float silu_f(float x) {
    return x * (1.0f / (1.0f + __expf(-x)));
}

__global__ __launch_bounds__(NT, 3) void fused_kernel(
    const float* __restrict__ af,      // (16384, 272)
    const float* __restrict__ W0,      // (T, 32, 256)
    const float* __restrict__ W1,      // (T, 64, 256)
    const float* __restrict__ Wo,      // (T, 64, 128)
    const int*   __restrict__ mapping, // (16384)
    float*       __restrict__ out)     // (NB, T*128)
{
    __shared__ float Wa[IN0 * HID];     // [k][o]  2048 f
    __shared__ float Wb[HID * HID];     // [k][o]  4096 f
    __shared__ float xs[IN0 * ATILE];   // [k][a]  2048 f (red[] aliases this)
    __shared__ float s1[HID * PADA];    // [k][a]  4352 f
    __shared__ int   aid[ATILE];

    const int t    = threadIdx.x;
    const int gtid = blockIdx.x * NT + t;

    // ===== phase 0: warp-aggregated counting-sort into 320 (b,cls) bins =====
    if (gtid < NATOMS) {
        int m = mapping[gtid];
        int b = gtid >> 9;                       // / 512
        int bin = b * NCLS + m;                  // valid only if m < NCLS
        unsigned peers  = __match_any_sync(0xffffffffu, m);  // same b in warp
        int lane   = t & 31;
        int leader = __ffs(peers) - 1;
        int rank   = __popc(peers & ((1u << lane) - 1u));
        int base   = 0;
        if (m < NCLS && lane == leader)
            base = atomicAdd(&g_cnt[bin], __popc(peers));
        base = __shfl_sync(0xffffffffu, base, leader);
        if (m < NCLS) g_list[bin * BINCAP + base + rank] = gtid;
    }

    // ===== epoch grid barrier (replay-safe, no reset needed) =====
    __syncthreads();
    if (t == 0) {
        __threadfence();
        unsigned old    = atomicAdd(&g_bar, 1u);
        unsigned target = old - (old % GRID) + GRID;
        while (*(volatile unsigned*)&g_bar < target) {}
    }
    __syncthreads();

    // ===== phase 1: this block owns bin = blockIdx.x =====
    const int bin = blockIdx.x;
    const int b   = bin / NCLS;
    const int cls = bin % NCLS;
    const int cnt = __ldcg(&g_cnt[bin]);
    __syncthreads();
    if (t == 0) g_cnt[bin] = 0;      // lifecycle reset (sole reader is us)

    const int a0 = (t & 15) << 2;    // 4-atom group
    const int o0 = (t >> 4) << 3;    // 8-output group
    float part[8];
    #pragma unroll
    for (int j = 0; j < 8; j++) part[j] = 0.0f;

    if (cnt > 0) {
        // stage weights into smem (live 64 cols of the 256-wide W0_0/W1_0)
        const float4* w0p = (const float4*)(W0 + (size_t)cls * IN0 * L0OUT);
        #pragma unroll
        for (int r = 0; r < 4; r++) {
            int idx = r * NT + t, k = idx >> 4, c = idx & 15;
            ((float4*)Wa)[k * 16 + c] = __ldg(&w0p[k * 64 + c]);
        }
        const float4* w1p = (const float4*)(W1 + (size_t)cls * HID * L0OUT);
        #pragma unroll
        for (int r = 0; r < 8; r++) {
            int idx = r * NT + t, k = idx >> 4, c = idx & 15;
            ((float4*)Wb)[k * 16 + c] = __ldg(&w1p[k * 64 + c]);
        }

        const float RS32 = 0.17677669529663687f;   // 1/sqrt(32)
        const int ntiles = (cnt + ATILE - 1) >> 6;

        for (int tile = 0; tile < ntiles; tile++) {
            // gather 64 atoms' scalar features, transposed [k][a]; pad -> 0
            if (t < ATILE) {
                int i  = tile * ATILE + t;
                int id = (i < cnt) ? __ldcg(&g_list[bin * BINCAP + i]) : -1;
                float4 row[8];
                if (id >= 0) {
                    const float4* ap = (const float4*)(af + (size_t)id * DIN);
                    #pragma unroll
                    for (int j = 0; j < 8; j++) row[j] = __ldg(&ap[j]);
                } else {
                    #pragma unroll
                    for (int j = 0; j < 8; j++)
                        row[j] = make_float4(0.f, 0.f, 0.f, 0.f);
                }
                #pragma unroll
                for (int j = 0; j < 8; j++) {
                    xs[(4 * j + 0) * ATILE + t] = row[j].x;
                    xs[(4 * j + 1) * ATILE + t] = row[j].y;
                    xs[(4 * j + 2) * ATILE + t] = row[j].z;
                    xs[(4 * j + 3) * ATILE + t] = row[j].w;
                }
            }
            __syncthreads();

            // ---- stage 1: [64a x 32k x 64o] ----
            float acc1[4][8];
            #pragma unroll
            for (int i = 0; i < 4; i++)
                #pragma unroll
                for (int j = 0; j < 8; j++) acc1[i][j] = 0.0f;
            #pragma unroll
            for (int k = 0; k < IN0; k++) {
                float4 x4 = *(const float4*)&xs[k * ATILE + a0];
                float4 wA = *(const float4*)&Wa[k * HID + o0];
                float4 wB = *(const float4*)&Wa[k * HID + o0 + 4];
                float xv[4] = {x4.x, x4.y, x4.z, x4.w};
                float wv[8] = {wA.x, wA.y, wA.z, wA.w, wB.x, wB.y, wB.z, wB.w};
                #pragma unroll
                for (int i = 0; i < 4; i++)
                    #pragma unroll
                    for (int j = 0; j < 8; j++) acc1[i][j] += xv[i] * wv[j];
            }
            #pragma unroll
            for (int j = 0; j < 8; j++) {     // silu + transpose to [o][a]
                float4 v;
                v.x = silu_f(acc1[0][j] * RS32);
                v.y = silu_f(acc1[1][j] * RS32);
                v.z = silu_f(acc1[2][j] * RS32);
                v.w = silu_f(acc1[3][j] * RS32);
                *(float4*)&s1[(o0 + j) * PADA + a0] = v;
            }
            __syncthreads();

            // ---- stage 2: [64a x 64k x 64o]; silu(0)=0 so pads are inert ----
            float acc2[4][8];
            #pragma unroll
            for (int i = 0; i < 4; i++)
                #pragma unroll
                for (int j = 0; j < 8; j++) acc2[i][j] = 0.0f;
            #pragma unroll
            for (int k = 0; k < HID; k++) {
                float4 x4 = *(const float4*)&s1[k * PADA + a0];
                float4 wA = *(const float4*)&Wb[k * HID + o0];
                float4 wB = *(const float4*)&Wb[k * HID + o0 + 4];
                float xv[4] = {x4.x, x4.y, x4.z, x4.w};
                float wv[8] = {wA.x, wA.y, wA.z, wA.w, wB.x, wB.y, wB.z, wB.w};
                #pragma unroll
                for (int i = 0; i < 4; i++)
                    #pragma unroll
                    for (int j = 0; j < 8; j++) acc2[i][j] += xv[i] * wv[j];
            }
            #pragma unroll
            for (int i = 0; i < 4; i++)
                #pragma unroll
                for (int j = 0; j < 8; j++)
                    part[j] += silu_f(acc2[i][j] * 0.125f);
            __syncthreads();   // s1/xs reused next tile
        }
    }

    // ===== reduce part[] over the 16 threads sharing an o-group =====
    #pragma unroll
    for (int off = 1; off < 16; off <<= 1)
        #pragma unroll
        for (int j = 0; j < 8; j++)
            part[j] += __shfl_xor_sync(0xffffffffu, part[j], off);

    float* red = xs;           // alias: xs dead after last stage-1
    __syncthreads();
    if ((t & 15) == 0) {
        #pragma unroll
        for (int j = 0; j < 8; j++) red[o0 + j] = part[j];
    }
    __syncthreads();

    // ===== final: out[b, cls*128 + t] = (red @ Wout[cls])[t] / 8 =====
    const float* wp = Wo + (size_t)cls * HID * NOUT + t;
    float s = 0.0f;
    #pragma unroll
    for (int h = 0; h < HID; h++)
        s += red[h] * __ldg(&wp[h * NOUT]);
    out[b * (NCLS * NOUT) + cls * NOUT + t] = 0.125f * s;
}

// ---------------------------------------------------------------------------
extern "C" void kernel_launch(void* const* d_in, const int* in_sizes, int n_in,
                              void* d_out, int out_size) {
    const float* af      = (const float*)d_in[0];   // atom_features
    const float* W0      = (const float*)d_in[1];   // W0_0
    const float* W1      = (const float*)d_in[5];   // W1_0
    const float* Wo      = (const float*)d_in[9];   // Wout
    const int*   mapping = (const int*)  d_in[10];  // mlp_mapping
    float* out = (float*)d_out;

    fused_kernel<<<GRID, NT>>>(af, W0, W1, Wo, mapping, out);
}

// round 5
// speedup vs baseline: 1.3350x; 1.3350x over previous
#include <cuda_runtime.h>
#include <cstdint>

#define NCLS   10
#define NB     32
#define NBINS  (NB * NCLS)      // 320
#define NATOMS 16384
#define DIN    272
#define HID    64
#define NOUT   128
#define L0OUT  256
#define IN0    32
#define ATILE  64
#define BINCAP 512
#define GRID   NBINS
#define NT     128
#define PADA   68               // s1 row stride (floats): 272B, shifts banks by 4

// static device scratch (module-init zero; replay-safe lifecycle below)
__device__ int      g_cnt[NBINS];
__device__ int      g_list[NBINS * BINCAP];
__device__ unsigned g_bar;      // monotonic epoch barrier counter

__device__ __forceinline__ float silu_f(float x) {
    return x * (1.0f / (1.0f + __expf(-x)));
}

// packed dual-fp32 FMA: d.lo += a.lo*b.lo ; d.hi += a.hi*b.hi  (FFMA2)
__device__ __forceinline__ void ffma2(unsigned long long& d,
                                      unsigned long long a,
                                      unsigned long long b) {
    asm("fma.rn.f32x2 %0, %1, %2, %0;" : "+l"(d) : "l"(a), "l"(b));
}
__device__ __forceinline__ float lo32(unsigned long long v) {
    return __uint_as_float((unsigned)(v & 0xffffffffull));
}
__device__ __forceinline__ float hi32(unsigned long long v) {
    return __uint_as_float((unsigned)(v >> 32));
}

__global__ __launch_bounds__(NT, 3) void fused_kernel(
    const float* __restrict__ af,      // (16384, 272)
    const float* __restrict__ W0,      // (T, 32, 256)
    const float* __restrict__ W1,      // (T, 64, 256)
    const float* __restrict__ Wo,      // (T, 64, 128)
    const int*   __restrict__ mapping, // (16384)
    float*       __restrict__ out)     // (NB, T*128)
{
    __shared__ float WaD[IN0 * 2 * HID];   // [k][(o,o) dup]  4096 f = 16KB
    __shared__ float WbD[HID * 2 * HID];   // [k][(o,o) dup]  8192 f = 32KB
    __shared__ float xs[IN0 * ATILE];      // [k][a]          2048 f =  8KB
    __shared__ float s1[HID * PADA];       // [k][a] padded   4352 f = 17KB

    const int t    = threadIdx.x;
    const int gtid = blockIdx.x * NT + t;

    // ===== phase 0: warp-aggregated counting-sort into 320 (b,cls) bins =====
    if (gtid < NATOMS) {
        int m = mapping[gtid];
        int b = gtid >> 9;
        int bin = b * NCLS + m;
        unsigned peers  = __match_any_sync(0xffffffffu, m);   // b uniform in warp
        int lane   = t & 31;
        int leader = __ffs(peers) - 1;
        int rank   = __popc(peers & ((1u << lane) - 1u));
        int base   = 0;
        if (m < NCLS && lane == leader)
            base = atomicAdd(&g_cnt[bin], __popc(peers));
        base = __shfl_sync(0xffffffffu, base, leader);
        if (m < NCLS) g_list[bin * BINCAP + base + rank] = gtid;
    }

    // ===== epoch grid barrier (replay-safe, all 320 blocks co-resident) =====
    __syncthreads();
    if (t == 0) {
        __threadfence();
        unsigned old    = atomicAdd(&g_bar, 1u);
        unsigned target = old - (old % GRID) + GRID;
        while (*(volatile unsigned*)&g_bar < target) {}
    }
    __syncthreads();

    // ===== phase 1: this block owns bin = blockIdx.x =====
    const int bin = blockIdx.x;
    const int b   = bin / NCLS;
    const int cls = bin % NCLS;
    const int cnt = __ldcg(&g_cnt[bin]);
    __syncthreads();
    if (t == 0) g_cnt[bin] = 0;          // lifecycle reset (sole reader is us)

    // micro-tile: 8 atoms (4 f32x2 pairs) x 4 outputs per thread
    const int a0 = (t & 7) * 8;
    const int o0 = (t >> 3) * 4;
    float part[4] = {0.f, 0.f, 0.f, 0.f};

    if (cnt > 0) {
        // ---- stage duplicated weights into smem: WaD[k][2o]=WaD[k][2o+1]=w ----
        const float4* w0p = (const float4*)(W0 + (size_t)cls * IN0 * L0OUT);
        #pragma unroll
        for (int r = 0; r < 4; r++) {                // 512 source float4s
            int idx = r * NT + t, k = idx >> 4, c = idx & 15;
            float4 w = __ldg(&w0p[k * 64 + c]);      // cols 4c..4c+3 of row k
            float* dst = &WaD[k * 128 + 8 * c];
            *(float4*)(dst)     = make_float4(w.x, w.x, w.y, w.y);
            *(float4*)(dst + 4) = make_float4(w.z, w.z, w.w, w.w);
        }
        const float4* w1p = (const float4*)(W1 + (size_t)cls * HID * L0OUT);
        #pragma unroll
        for (int r = 0; r < 8; r++) {                // 1024 source float4s
            int idx = r * NT + t, k = idx >> 4, c = idx & 15;
            float4 w = __ldg(&w1p[k * 64 + c]);
            float* dst = &WbD[k * 128 + 8 * c];
            *(float4*)(dst)     = make_float4(w.x, w.x, w.y, w.y);
            *(float4*)(dst + 4) = make_float4(w.z, w.z, w.w, w.w);
        }

        const float RS32 = 0.17677669529663687f;     // 1/sqrt(32)
        const int ntiles = (cnt + ATILE - 1) >> 6;

        for (int tile = 0; tile < ntiles; tile++) {
            // ---- gather 64 atoms' first-32 features, transposed [k][a] ----
            {
                int a    = t >> 1;                   // atom slot 0..63
                int half = t & 1;                    // feature half 0/1
                int i    = tile * ATILE + a;
                int id   = (i < cnt) ? __ldcg(&g_list[bin * BINCAP + i]) : -1;
                float4 row[4];
                if (id >= 0) {
                    const float4* ap =
                        (const float4*)(af + (size_t)id * DIN + half * 16);
                    #pragma unroll
                    for (int j = 0; j < 4; j++) row[j] = __ldg(&ap[j]);
                } else {
                    #pragma unroll
                    for (int j = 0; j < 4; j++)
                        row[j] = make_float4(0.f, 0.f, 0.f, 0.f);
                }
                int kb = half * 16;
                #pragma unroll
                for (int j = 0; j < 4; j++) {
                    xs[(kb + 4 * j + 0) * ATILE + a] = row[j].x;
                    xs[(kb + 4 * j + 1) * ATILE + a] = row[j].y;
                    xs[(kb + 4 * j + 2) * ATILE + a] = row[j].z;
                    xs[(kb + 4 * j + 3) * ATILE + a] = row[j].w;
                }
            }
            __syncthreads();

            // ---- stage 1: [64a x 32k x 64o], FFMA2 over atom pairs ----
            unsigned long long acc1[4][4] = {};
            #pragma unroll
            for (int k = 0; k < IN0; k++) {
                ulonglong2 xA = *(const ulonglong2*)&xs[k * ATILE + a0];
                ulonglong2 xB = *(const ulonglong2*)&xs[k * ATILE + a0 + 4];
                ulonglong2 wA = *(const ulonglong2*)&WaD[k * 128 + 2 * o0];
                ulonglong2 wB = *(const ulonglong2*)&WaD[k * 128 + 2 * o0 + 4];
                unsigned long long xp[4] = {xA.x, xA.y, xB.x, xB.y};
                unsigned long long wp[4] = {wA.x, wA.y, wB.x, wB.y};
                #pragma unroll
                for (int i = 0; i < 4; i++)
                    #pragma unroll
                    for (int j = 0; j < 4; j++)
                        ffma2(acc1[i][j], xp[i], wp[j]);
            }
            // silu + transposed store to s1[o][a] (atom pairs stay packed)
            #pragma unroll
            for (int j = 0; j < 4; j++) {
                float4 v0, v1;
                v0.x = silu_f(lo32(acc1[0][j]) * RS32);
                v0.y = silu_f(hi32(acc1[0][j]) * RS32);
                v0.z = silu_f(lo32(acc1[1][j]) * RS32);
                v0.w = silu_f(hi32(acc1[1][j]) * RS32);
                v1.x = silu_f(lo32(acc1[2][j]) * RS32);
                v1.y = silu_f(hi32(acc1[2][j]) * RS32);
                v1.z = silu_f(lo32(acc1[3][j]) * RS32);
                v1.w = silu_f(hi32(acc1[3][j]) * RS32);
                *(float4*)&s1[(o0 + j) * PADA + a0]     = v0;
                *(float4*)&s1[(o0 + j) * PADA + a0 + 4] = v1;
            }
            __syncthreads();

            // ---- stage 2: [64a x 64k x 64o], FFMA2; pads are exact zeros ----
            unsigned long long acc2[4][4] = {};
            #pragma unroll
            for (int k = 0; k < HID; k++) {
                ulonglong2 xA = *(const ulonglong2*)&s1[k * PADA + a0];
                ulonglong2 xB = *(const ulonglong2*)&s1[k * PADA + a0 + 4];
                ulonglong2 wA = *(const ulonglong2*)&WbD[k * 128 + 2 * o0];
                ulonglong2 wB = *(const ulonglong2*)&WbD[k * 128 + 2 * o0 + 4];
                unsigned long long xp[4] = {xA.x, xA.y, xB.x, xB.y};
                unsigned long long wp[4] = {wA.x, wA.y, wB.x, wB.y};
                #pragma unroll
                for (int i = 0; i < 4; i++)
                    #pragma unroll
                    for (int j = 0; j < 4; j++)
                        ffma2(acc2[i][j], xp[i], wp[j]);
            }
            #pragma unroll
            for (int j = 0; j < 4; j++)
                #pragma unroll
                for (int i = 0; i < 4; i++)
                    part[j] += silu_f(lo32(acc2[i][j]) * 0.125f)
                             + silu_f(hi32(acc2[i][j]) * 0.125f);
            __syncthreads();    // s1/xs reused next tile
        }
    }

    // ===== reduce part[] over the 8 atom-groups (lanes differing in t&7) =====
    #pragma unroll
    for (int off = 1; off < 8; off <<= 1)
        #pragma unroll
        for (int j = 0; j < 4; j++)
            part[j] += __shfl_xor_sync(0xffffffffu, part[j], off);

    float* red = xs;            // alias: xs dead now
    __syncthreads();
    if ((t & 7) == 0) {
        #pragma unroll
        for (int j = 0; j < 4; j++) red[o0 + j] = part[j];
    }
    __syncthreads();

    // ===== final: out[b, cls*128 + t] = (red @ Wout[cls])[t] / 8 =====
    const float* wp = Wo + (size_t)cls * HID * NOUT + t;
    float s = 0.0f;
    #pragma unroll
    for (int h = 0; h < HID; h++)
        s += red[h] * __ldg(&wp[h * NOUT]);
    out[b * (NCLS * NOUT) + cls * NOUT + t] = 0.125f * s;
}

// ---------------------------------------------------------------------------
extern "C" void kernel_launch(void* const* d_in, const int* in_sizes, int n_in,
                              void* d_out, int out_size) {
    const float* af      = (const float*)d_in[0];   // atom_features
    const float* W0      = (const float*)d_in[1];   // W0_0
    const float* W1      = (const float*)d_in[5];   // W1_0
    const float* Wo      = (const float*)d_in[9];   // Wout
    const int*   mapping = (const int*)  d_in[10];  // mlp_mapping
    float* out = (float*)d_out;

    fused_kernel<<<GRID, NT>>>(af, W0, W1, Wo, mapping, out);
}

// round 7
// speedup vs baseline: 1.6641x; 1.2465x over previous
#include <cuda_runtime.h>
#include <cstdint>

#define NCLS   10
#define NB     32
#define NBINS  (NB * NCLS)      // 320
#define NATOMS 16384
#define DIN    272
#define HID    64
#define NOUT   128
#define L0OUT  256
#define IN0    32
#define ATILE  64
#define BINCAP 512
#define NT     256
#define PADA   68               // s1 row stride (floats)

// static device scratch (module-init zero; replay-safe lifecycle below)
__device__ int g_cnt[NBINS];
__device__ int g_list[NBINS * BINCAP];

__device__ __forceinline__ float silu_f(float x) {
    return x * (1.0f / (1.0f + __expf(-x)));
}

// packed dual-fp32 FMA: d.lo += a.lo*b.lo ; d.hi += a.hi*b.hi
__device__ __forceinline__ void ffma2(unsigned long long& d,
                                      unsigned long long a,
                                      unsigned long long b) {
    asm("fma.rn.f32x2 %0, %1, %2, %0;" : "+l"(d) : "l"(a), "l"(b));
}
__device__ __forceinline__ float lo32(unsigned long long v) {
    return __uint_as_float((unsigned)(v & 0xffffffffull));
}
__device__ __forceinline__ float hi32(unsigned long long v) {
    return __uint_as_float((unsigned)(v >> 32));
}

// ===========================================================================
// Kernel A: warp-aggregated counting-sort into 320 (b, cls) bins
// ===========================================================================
__global__ __launch_bounds__(128) void classify_kernel(
    const int* __restrict__ mapping)
{
    int gtid = blockIdx.x * 128 + threadIdx.x;      // 0..16383
    int m = mapping[gtid];
    int b = gtid >> 9;                              // batch (warp-uniform)
    int bin = b * NCLS + m;
    unsigned peers  = __match_any_sync(0xffffffffu, m);
    int lane   = threadIdx.x & 31;
    int leader = __ffs(peers) - 1;
    int rank   = __popc(peers & ((1u << lane) - 1u));
    int base   = 0;
    if (m < NCLS && lane == leader)
        base = atomicAdd(&g_cnt[bin], __popc(peers));
    base = __shfl_sync(0xffffffffu, base, leader);
    if (m < NCLS) g_list[bin * BINCAP + base + rank] = gtid;
}

// ===========================================================================
// Kernel B: per-bin fused MLP. Block = bin (b, cls), 256 threads.
//   s1 = silu((x32 @ W0a)/sqrt32); s2 = silu((s1 @ W1a)/8)
//   red = sum_atoms s2;  out[b, cls*128+o] = (red @ Wout[cls])/8
// Micro-tile 4 atoms (2 f32x2 pairs) x 4 outputs, FFMA2 throughout.
// ===========================================================================
__global__ __launch_bounds__(NT, 2) void mlp_kernel(
    const float* __restrict__ af,      // (16384, 272)
    const float* __restrict__ W0,      // (T, 32, 256)
    const float* __restrict__ W1,      // (T, 64, 256)
    const float* __restrict__ Wo,      // (T, 64, 128)
    float*       __restrict__ out)     // (NB, T*128)
{
    __shared__ float WaD[IN0 * 2 * HID];   // [k][(o,o) dup]  16KB
    __shared__ float WbD[HID * 2 * HID];   // [k][(o,o) dup]  32KB
    __shared__ float xs[IN0 * ATILE];      // [k][a]           8KB
    __shared__ float s1[HID * PADA];       // [k][a] padded   17KB
    __shared__ int   s_cnt;

    const int t   = threadIdx.x;
    const int bin = blockIdx.x;
    const int b   = bin / NCLS;
    const int cls = bin % NCLS;

    // RACE-SAFE count read + lifecycle reset: same thread reads then writes
    // (program order); all other threads wait at the barrier before reading
    // the shared copy. No other agent touches g_cnt[bin] between kernels.
    if (t == 0) {
        s_cnt = __ldcg(&g_cnt[bin]);
        g_cnt[bin] = 0;
    }
    __syncthreads();
    const int cnt = s_cnt;

    // micro-tile coordinates
    const int a0 = (t & 15) << 2;          // 4-atom group (2 pairs)
    const int o0 = (t >> 4) << 2;          // 4-output group
    float part[4] = {0.f, 0.f, 0.f, 0.f};

    if (cnt > 0) {
        // ---- stage duplicated weights: WaD[k][2o]=WaD[k][2o+1]=w ----
        const float4* w0p = (const float4*)(W0 + (size_t)cls * IN0 * L0OUT);
        #pragma unroll
        for (int r = 0; r < 2; r++) {              // 512 source float4s
            int idx = r * NT + t, k = idx >> 4, c = idx & 15;
            float4 w = __ldg(&w0p[k * 64 + c]);
            float* dst = &WaD[k * 128 + 8 * c];
            *(float4*)(dst)     = make_float4(w.x, w.x, w.y, w.y);
            *(float4*)(dst + 4) = make_float4(w.z, w.z, w.w, w.w);
        }
        const float4* w1p = (const float4*)(W1 + (size_t)cls * HID * L0OUT);
        #pragma unroll
        for (int r = 0; r < 4; r++) {              // 1024 source float4s
            int idx = r * NT + t, k = idx >> 4, c = idx & 15;
            float4 w = __ldg(&w1p[k * 64 + c]);
            float* dst = &WbD[k * 128 + 8 * c];
            *(float4*)(dst)     = make_float4(w.x, w.x, w.y, w.y);
            *(float4*)(dst + 4) = make_float4(w.z, w.z, w.w, w.w);
        }

        const float RS32 = 0.17677669529663687f;   // 1/sqrt(32)
        const int ntiles = (cnt + ATILE - 1) >> 6;

        for (int tile = 0; tile < ntiles; tile++) {
            // ---- gather 64 atoms' first-32 features, transposed [k][a] ----
            {
                int a = t >> 2, q = t & 3;         // atom slot, feature quarter
                int i = tile * ATILE + a;
                int id = (i < cnt) ? __ldcg(&g_list[bin * BINCAP + i]) : -1;
                float4 r0, r1;
                if (id >= 0) {
                    const float4* ap =
                        (const float4*)(af + (size_t)id * DIN + q * 8);
                    r0 = __ldg(&ap[0]);
                    r1 = __ldg(&ap[1]);
                } else {
                    r0 = make_float4(0.f, 0.f, 0.f, 0.f);
                    r1 = r0;
                }
                int kb = q * 8;
                xs[(kb + 0) * ATILE + a] = r0.x;
                xs[(kb + 1) * ATILE + a] = r0.y;
                xs[(kb + 2) * ATILE + a] = r0.z;
                xs[(kb + 3) * ATILE + a] = r0.w;
                xs[(kb + 4) * ATILE + a] = r1.x;
                xs[(kb + 5) * ATILE + a] = r1.y;
                xs[(kb + 6) * ATILE + a] = r1.z;
                xs[(kb + 7) * ATILE + a] = r1.w;
            }
            __syncthreads();

            // ---- stage 1: [64a x 32k x 64o], FFMA2 ----
            unsigned long long acc1[2][4] = {};
            #pragma unroll
            for (int k = 0; k < IN0; k++) {
                ulonglong2 xA = *(const ulonglong2*)&xs[k * ATILE + a0];
                ulonglong2 wA = *(const ulonglong2*)&WaD[k * 128 + 2 * o0];
                ulonglong2 wB = *(const ulonglong2*)&WaD[k * 128 + 2 * o0 + 4];
                unsigned long long xp[2] = {xA.x, xA.y};
                unsigned long long wp[4] = {wA.x, wA.y, wB.x, wB.y};
                #pragma unroll
                for (int i = 0; i < 2; i++)
                    #pragma unroll
                    for (int j = 0; j < 4; j++)
                        ffma2(acc1[i][j], xp[i], wp[j]);
            }
            // silu + transposed store to s1[o][a]
            #pragma unroll
            for (int j = 0; j < 4; j++) {
                float4 v;
                v.x = silu_f(lo32(acc1[0][j]) * RS32);
                v.y = silu_f(hi32(acc1[0][j]) * RS32);
                v.z = silu_f(lo32(acc1[1][j]) * RS32);
                v.w = silu_f(hi32(acc1[1][j]) * RS32);
                *(float4*)&s1[(o0 + j) * PADA + a0] = v;
            }
            __syncthreads();

            // ---- stage 2: [64a x 64k x 64o], FFMA2; pads are exact zeros ----
            unsigned long long acc2[2][4] = {};
            #pragma unroll
            for (int k = 0; k < HID; k++) {
                ulonglong2 xA = *(const ulonglong2*)&s1[k * PADA + a0];
                ulonglong2 wA = *(const ulonglong2*)&WbD[k * 128 + 2 * o0];
                ulonglong2 wB = *(const ulonglong2*)&WbD[k * 128 + 2 * o0 + 4];
                unsigned long long xp[2] = {xA.x, xA.y};
                unsigned long long wp[4] = {wA.x, wA.y, wB.x, wB.y};
                #pragma unroll
                for (int i = 0; i < 2; i++)
                    #pragma unroll
                    for (int j = 0; j < 4; j++)
                        ffma2(acc2[i][j], xp[i], wp[j]);
            }
            #pragma unroll
            for (int j = 0; j < 4; j++)
                #pragma unroll
                for (int i = 0; i < 2; i++)
                    part[j] += silu_f(lo32(acc2[i][j]) * 0.125f)
                             + silu_f(hi32(acc2[i][j]) * 0.125f);
            __syncthreads();   // s1/xs reused next tile
        }
    }

    // ===== reduce part[] over the 16 atom-groups (in-warp: t&15) =====
    #pragma unroll
    for (int off = 1; off < 16; off <<= 1)
        #pragma unroll
        for (int j = 0; j < 4; j++)
            part[j] += __shfl_xor_sync(0xffffffffu, part[j], off);

    float* red = xs;           // alias: xs dead now
    __syncthreads();
    if ((t & 15) == 0) {
        #pragma unroll
        for (int j = 0; j < 4; j++) red[o0 + j] = part[j];
    }
    __syncthreads();

    // ===== final: out[b, cls*128 + o] = (red @ Wout[cls])[o] / 8 =====
    if (t < NOUT) {
        const float* wp = Wo + (size_t)cls * HID * NOUT + t;
        float s = 0.0f;
        #pragma unroll
        for (int h = 0; h < HID; h++)
            s += red[h] * __ldg(&wp[h * NOUT]);
        out[b * (NCLS * NOUT) + cls * NOUT + t] = 0.125f * s;
    }
}

// ---------------------------------------------------------------------------
extern "C" void kernel_launch(void* const* d_in, const int* in_sizes, int n_in,
                              void* d_out, int out_size) {
    const float* af      = (const float*)d_in[0];   // atom_features
    const float* W0      = (const float*)d_in[1];   // W0_0
    const float* W1      = (const float*)d_in[5];   // W1_0
    const float* Wo      = (const float*)d_in[9];   // Wout
    const int*   mapping = (const int*)  d_in[10];  // mlp_mapping
    float* out = (float*)d_out;

    classify_kernel<<<NATOMS / 128, 128>>>(mapping);
    mlp_kernel<<<NBINS, NT>>>(af, W0, W1, Wo, out);
}

// round 8
// speedup vs baseline: 1.8430x; 1.1075x over previous
#include <cuda_runtime.h>
#include <cstdint>

#define NCLS   10
#define NB     32
#define NBINS  (NB * NCLS)      // 320
#define NATOMS 16384
#define DIN    272
#define HID    64
#define NOUT   128
#define L0OUT  256
#define IN0    32
#define ATILE  64
#define BINCAP 512
#define NT     256
#define PADA   68               // s1 row stride (floats)

// static device scratch (module-init zero; replay-safe lifecycle below)
__device__ int g_cnt[NBINS];
__device__ int g_list[NBINS * BINCAP];

__device__ __forceinline__ float silu_f(float x) {
    return x * (1.0f / (1.0f + __expf(-x)));
}

// packed dual-fp32 FMA: d.lo += a.lo*b.lo ; d.hi += a.hi*b.hi
__device__ __forceinline__ void ffma2(unsigned long long& d,
                                      unsigned long long a,
                                      unsigned long long b) {
    asm("fma.rn.f32x2 %0, %1, %2, %0;" : "+l"(d) : "l"(a), "l"(b));
}
__device__ __forceinline__ unsigned long long pack2(float x) {
    unsigned long long r;
    asm("mov.b64 %0, {%1, %1};" : "=l"(r) : "f"(x));
    return r;
}
__device__ __forceinline__ float lo32(unsigned long long v) {
    return __uint_as_float((unsigned)(v & 0xffffffffull));
}
__device__ __forceinline__ float hi32(unsigned long long v) {
    return __uint_as_float((unsigned)(v >> 32));
}

// ===========================================================================
// Kernel A: warp-aggregated counting-sort into 320 (b, cls) bins
// ===========================================================================
__global__ __launch_bounds__(128) void classify_kernel(
    const int* __restrict__ mapping)
{
    int gtid = blockIdx.x * 128 + threadIdx.x;      // 0..16383
    int m = mapping[gtid];
    int b = gtid >> 9;                              // batch (warp-uniform)
    int bin = b * NCLS + m;
    unsigned peers  = __match_any_sync(0xffffffffu, m);
    int lane   = threadIdx.x & 31;
    int leader = __ffs(peers) - 1;
    int rank   = __popc(peers & ((1u << lane) - 1u));
    int base   = 0;
    if (m < NCLS && lane == leader)
        base = atomicAdd(&g_cnt[bin], __popc(peers));
    base = __shfl_sync(0xffffffffu, base, leader);
    if (m < NCLS) g_list[bin * BINCAP + base + rank] = gtid;
}

// ===========================================================================
// Kernel B: per-bin fused MLP. Block = bin (b, cls), 256 threads, 3 CTAs/SM.
// f32x2 lanes carry OUTPUT pairs: weights natural in smem (adjacent o = ready
// pair), x duplicated per-register via mov.b64 {x,x}. 2 LDS.128 per k.
// ===========================================================================
__global__ __launch_bounds__(NT, 3) void mlp_kernel(
    const float* __restrict__ af,      // (16384, 272)
    const float* __restrict__ W0,      // (T, 32, 256)
    const float* __restrict__ W1,      // (T, 64, 256)
    const float* __restrict__ Wo,      // (T, 64, 128)
    float*       __restrict__ out)     // (NB, T*128)
{
    __shared__ float WaN[IN0 * HID];     // [k][o] natural   8KB
    __shared__ float WbN[HID * HID];     // [k][o] natural  16KB
    __shared__ float xs[IN0 * ATILE];    // [k][a]           8KB
    __shared__ float s1[HID * PADA];     // [k][a] padded   17KB
    __shared__ int   s_cnt;

    const int t   = threadIdx.x;
    const int bin = blockIdx.x;
    const int b   = bin / NCLS;
    const int cls = bin % NCLS;

    // race-safe count read + lifecycle reset (single thread, program order)
    if (t == 0) {
        s_cnt = __ldcg(&g_cnt[bin]);
        g_cnt[bin] = 0;
    }
    __syncthreads();
    const int cnt = s_cnt;

    // micro-tile: 4 atoms x 4 outputs (2 o-pairs) per thread
    const int a0 = (t & 15) << 2;
    const int o0 = (t >> 4) << 2;
    float part[4] = {0.f, 0.f, 0.f, 0.f};

    if (cnt > 0) {
        // ---- stage natural weights (first 64 live cols of 256) ----
        const float4* w0p = (const float4*)(W0 + (size_t)cls * IN0 * L0OUT);
        #pragma unroll
        for (int r = 0; r < 2; r++) {               // 512 float4s
            int idx = r * NT + t, k = idx >> 4, c = idx & 15;
            ((float4*)WaN)[k * 16 + c] = __ldg(&w0p[k * 64 + c]);
        }
        const float4* w1p = (const float4*)(W1 + (size_t)cls * HID * L0OUT);
        #pragma unroll
        for (int r = 0; r < 4; r++) {               // 1024 float4s
            int idx = r * NT + t, k = idx >> 4, c = idx & 15;
            ((float4*)WbN)[k * 16 + c] = __ldg(&w1p[k * 64 + c]);
        }

        const float RS32 = 0.17677669529663687f;    // 1/sqrt(32)
        const int ntiles = (cnt + ATILE - 1) >> 6;

        for (int tile = 0; tile < ntiles; tile++) {
            // ---- gather 64 atoms' first-32 features, transposed [k][a] ----
            {
                int a = t >> 2, q = t & 3;          // atom slot, feature quarter
                int i = tile * ATILE + a;
                int id = (i < cnt) ? __ldcg(&g_list[bin * BINCAP + i]) : -1;
                float4 r0, r1;
                if (id >= 0) {
                    const float4* ap =
                        (const float4*)(af + (size_t)id * DIN + q * 8);
                    r0 = __ldg(&ap[0]);
                    r1 = __ldg(&ap[1]);
                } else {
                    r0 = make_float4(0.f, 0.f, 0.f, 0.f);
                    r1 = r0;
                }
                int kb = q * 8;
                xs[(kb + 0) * ATILE + a] = r0.x;
                xs[(kb + 1) * ATILE + a] = r0.y;
                xs[(kb + 2) * ATILE + a] = r0.z;
                xs[(kb + 3) * ATILE + a] = r0.w;
                xs[(kb + 4) * ATILE + a] = r1.x;
                xs[(kb + 5) * ATILE + a] = r1.y;
                xs[(kb + 6) * ATILE + a] = r1.z;
                xs[(kb + 7) * ATILE + a] = r1.w;
            }
            __syncthreads();

            // ---- stage 1: [64a x 32k x 64o], o-paired FFMA2 ----
            unsigned long long acc1[4][2] = {};
            #pragma unroll
            for (int k = 0; k < IN0; k++) {
                float4 xv = *(const float4*)&xs[k * ATILE + a0];
                ulonglong2 wv = *(const ulonglong2*)&WaN[k * HID + o0];
                unsigned long long xd[4] = {pack2(xv.x), pack2(xv.y),
                                            pack2(xv.z), pack2(xv.w)};
                #pragma unroll
                for (int i = 0; i < 4; i++) {
                    ffma2(acc1[i][0], xd[i], wv.x);
                    ffma2(acc1[i][1], xd[i], wv.y);
                }
            }
            // silu + scalar transposed store: s1[o][a]
            #pragma unroll
            for (int i = 0; i < 4; i++) {
                #pragma unroll
                for (int p = 0; p < 2; p++) {
                    s1[(o0 + 2 * p)     * PADA + a0 + i] =
                        silu_f(lo32(acc1[i][p]) * RS32);
                    s1[(o0 + 2 * p + 1) * PADA + a0 + i] =
                        silu_f(hi32(acc1[i][p]) * RS32);
                }
            }
            __syncthreads();

            // ---- stage 2: [64a x 64k x 64o]; pads are exact zeros ----
            unsigned long long acc2[4][2] = {};
            #pragma unroll
            for (int k = 0; k < HID; k++) {
                float4 xv = *(const float4*)&s1[k * PADA + a0];
                ulonglong2 wv = *(const ulonglong2*)&WbN[k * HID + o0];
                unsigned long long xd[4] = {pack2(xv.x), pack2(xv.y),
                                            pack2(xv.z), pack2(xv.w)};
                #pragma unroll
                for (int i = 0; i < 4; i++) {
                    ffma2(acc2[i][0], xd[i], wv.x);
                    ffma2(acc2[i][1], xd[i], wv.y);
                }
            }
            #pragma unroll
            for (int i = 0; i < 4; i++) {
                #pragma unroll
                for (int p = 0; p < 2; p++) {
                    part[2 * p]     += silu_f(lo32(acc2[i][p]) * 0.125f);
                    part[2 * p + 1] += silu_f(hi32(acc2[i][p]) * 0.125f);
                }
            }
            __syncthreads();   // s1/xs reused next tile
        }
    }

    // ===== reduce part[] over the 16 atom-groups (in-warp, bits 0-3) =====
    #pragma unroll
    for (int off = 1; off < 16; off <<= 1)
        #pragma unroll
        for (int j = 0; j < 4; j++)
            part[j] += __shfl_xor_sync(0xffffffffu, part[j], off);

    float* red = xs;           // alias: xs dead now
    __syncthreads();
    if ((t & 15) == 0) {
        #pragma unroll
        for (int j = 0; j < 4; j++) red[o0 + j] = part[j];
    }
    __syncthreads();

    // ===== final: out[b, cls*128 + o] = (red @ Wout[cls])[o] / 8 =====
    if (t < NOUT) {
        const float* wp = Wo + (size_t)cls * HID * NOUT + t;
        float s = 0.0f;
        #pragma unroll
        for (int h = 0; h < HID; h++)
            s += red[h] * __ldg(&wp[h * NOUT]);
        out[b * (NCLS * NOUT) + cls * NOUT + t] = 0.125f * s;
    }
}

// ---------------------------------------------------------------------------
extern "C" void kernel_launch(void* const* d_in, const int* in_sizes, int n_in,
                              void* d_out, int out_size) {
    const float* af      = (const float*)d_in[0];   // atom_features
    const float* W0      = (const float*)d_in[1];   // W0_0
    const float* W1      = (const float*)d_in[5];   // W1_0
    const float* Wo      = (const float*)d_in[9];   // Wout
    const int*   mapping = (const int*)  d_in[10];  // mlp_mapping
    float* out = (float*)d_out;

    classify_kernel<<<NATOMS / 128, 128>>>(mapping);
    mlp_kernel<<<NBINS, NT>>>(af, W0, W1, Wo, out);
}

// round 9
// speedup vs baseline: 1.9078x; 1.0351x over previous
#include <cuda_runtime.h>
#include <cstdint>

#define NCLS   10
#define NB     32
#define NBINS  (NB * NCLS)      // 320
#define NATOMS 16384
#define DIN    272
#define HID    64
#define NOUT   128
#define L0OUT  256
#define IN0    32
#define ATILE  32               // atoms per half-bin tile
#define BINCAP 512
#define NT     256
#define PADA   36               // s1 row stride (floats), 144B

// static device scratch (module-init zero; replay-safe lifecycle below)
__device__ int g_cnt[NBINS];
__device__ int g_done[NBINS];
__device__ int g_list[NBINS * BINCAP];

__device__ __forceinline__ float silu_f(float x) {
    return x * (1.0f / (1.0f + __expf(-x)));
}

// packed dual-fp32 FMA: d.lo += a.lo*b.lo ; d.hi += a.hi*b.hi
__device__ __forceinline__ void ffma2(unsigned long long& d,
                                      unsigned long long a,
                                      unsigned long long b) {
    asm("fma.rn.f32x2 %0, %1, %2, %0;" : "+l"(d) : "l"(a), "l"(b));
}
__device__ __forceinline__ unsigned long long pack2(float x) {
    unsigned long long r;
    asm("mov.b64 %0, {%1, %1};" : "=l"(r) : "f"(x));
    return r;
}
__device__ __forceinline__ float lo32(unsigned long long v) {
    return __uint_as_float((unsigned)(v & 0xffffffffull));
}
__device__ __forceinline__ float hi32(unsigned long long v) {
    return __uint_as_float((unsigned)(v >> 32));
}

// ===========================================================================
// Kernel A: warp-aggregated counting-sort into 320 (b, cls) bins + zero out
// ===========================================================================
__global__ __launch_bounds__(128) void classify_kernel(
    const int* __restrict__ mapping,
    float* __restrict__ out)
{
    int gtid = blockIdx.x * 128 + threadIdx.x;      // 0..16383
    // zero the output accumulator (40960 floats)
    out[gtid]          = 0.0f;
    out[gtid + 16384]  = 0.0f;
    if (gtid < 8192) out[gtid + 32768] = 0.0f;

    int m = mapping[gtid];
    int b = gtid >> 9;                              // batch (warp-uniform)
    int bin = b * NCLS + m;
    unsigned peers  = __match_any_sync(0xffffffffu, m);
    int lane   = threadIdx.x & 31;
    int leader = __ffs(peers) - 1;
    int rank   = __popc(peers & ((1u << lane) - 1u));
    int base   = 0;
    if (m < NCLS && lane == leader)
        base = atomicAdd(&g_cnt[bin], __popc(peers));
    base = __shfl_sync(0xffffffffu, base, leader);
    if (m < NCLS) g_list[bin * BINCAP + base + rank] = gtid;
}

// ===========================================================================
// Kernel B: per half-bin fused MLP. Block (bin, half), 256 threads.
// 32-atom tiles strided by 64 within the bin's list. Partial output is
// atomically added into out (exactly 2 commutative adds per element).
// Micro-tile 2 atoms x 4 outputs (2 o-pairs), FFMA2 throughout.
// ===========================================================================
__global__ __launch_bounds__(NT, 4) void mlp_kernel(
    const float* __restrict__ af,      // (16384, 272)
    const float* __restrict__ W0,      // (T, 32, 256)
    const float* __restrict__ W1,      // (T, 64, 256)
    const float* __restrict__ Wo,      // (T, 64, 128)
    float*       __restrict__ out)     // (NB, T*128)
{
    __shared__ float WaN[IN0 * HID];     // [k][o] natural   8KB
    __shared__ float WbN[HID * HID];     // [k][o] natural  16KB
    __shared__ float xs[IN0 * ATILE];    // [k][a]           4KB
    __shared__ float s1[HID * PADA];     // [k][a] padded    9KB
    __shared__ int   s_cnt;

    const int t    = threadIdx.x;
    const int bin  = blockIdx.x >> 1;
    const int half = blockIdx.x & 1;
    const int b    = bin / NCLS;
    const int cls  = bin % NCLS;

    // race-safe count read; LAST of the two readers resets g_cnt and g_done.
    if (t == 0) {
        int c = __ldcg(&g_cnt[bin]);
        s_cnt = c;
        __threadfence();                        // order load before the atomic
        int old = atomicAdd(&g_done[bin], 1);
        if (old == 1) {                         // I'm the second reader
            __stcg(&g_cnt[bin], 0);
            __stcg(&g_done[bin], 0);
        }
    }
    __syncthreads();
    const int cnt = s_cnt;

    // micro-tile: 2 atoms x 4 outputs per thread
    const int a0 = (t & 15) << 1;               // atom pair base (0..30)
    const int o0 = (t >> 4) << 2;               // output quad base (0..60)
    float part[4] = {0.f, 0.f, 0.f, 0.f};

    if (cnt > half * ATILE) {
        // ---- stage natural weights (first 64 live cols of 256) ----
        const float4* w0p = (const float4*)(W0 + (size_t)cls * IN0 * L0OUT);
        #pragma unroll
        for (int r = 0; r < 2; r++) {           // 512 float4s
            int idx = r * NT + t, k = idx >> 4, c = idx & 15;
            ((float4*)WaN)[k * 16 + c] = __ldg(&w0p[k * 64 + c]);
        }
        const float4* w1p = (const float4*)(W1 + (size_t)cls * HID * L0OUT);
        #pragma unroll
        for (int r = 0; r < 4; r++) {           // 1024 float4s
            int idx = r * NT + t, k = idx >> 4, c = idx & 15;
            ((float4*)WbN)[k * 16 + c] = __ldg(&w1p[k * 64 + c]);
        }

        const float RS32 = 0.17677669529663687f;   // 1/sqrt(32)

        for (int start = half * ATILE; start < cnt; start += 2 * ATILE) {
            // ---- gather 32 atoms' first-32 features, transposed [k][a] ----
            {
                int a = t >> 3, q = t & 7;      // atom slot, feature eighth
                int i = start + a;
                int id = (i < cnt) ? __ldcg(&g_list[bin * BINCAP + i]) : -1;
                float4 r0;
                if (id >= 0) {
                    r0 = __ldg((const float4*)(af + (size_t)id * DIN + q * 4));
                } else {
                    r0 = make_float4(0.f, 0.f, 0.f, 0.f);
                }
                int kb = q * 4;
                xs[(kb + 0) * ATILE + a] = r0.x;
                xs[(kb + 1) * ATILE + a] = r0.y;
                xs[(kb + 2) * ATILE + a] = r0.z;
                xs[(kb + 3) * ATILE + a] = r0.w;
            }
            __syncthreads();

            // ---- stage 1: [32a x 32k x 64o], o-paired FFMA2 ----
            unsigned long long acc1[2][2] = {};
            #pragma unroll
            for (int k = 0; k < IN0; k++) {
                float2 xv = *(const float2*)&xs[k * ATILE + a0];
                ulonglong2 wv = *(const ulonglong2*)&WaN[k * HID + o0];
                unsigned long long x0 = pack2(xv.x), x1 = pack2(xv.y);
                ffma2(acc1[0][0], x0, wv.x);
                ffma2(acc1[0][1], x0, wv.y);
                ffma2(acc1[1][0], x1, wv.x);
                ffma2(acc1[1][1], x1, wv.y);
            }
            // silu + transposed store: 4 STS.64 (rows o, atom pairs)
            #pragma unroll
            for (int p = 0; p < 2; p++) {
                float2 vlo, vhi;
                vlo.x = silu_f(lo32(acc1[0][p]) * RS32);
                vlo.y = silu_f(lo32(acc1[1][p]) * RS32);
                vhi.x = silu_f(hi32(acc1[0][p]) * RS32);
                vhi.y = silu_f(hi32(acc1[1][p]) * RS32);
                *(float2*)&s1[(o0 + 2 * p)     * PADA + a0] = vlo;
                *(float2*)&s1[(o0 + 2 * p + 1) * PADA + a0] = vhi;
            }
            __syncthreads();

            // ---- stage 2: [32a x 64k x 64o]; pads are exact zeros ----
            unsigned long long acc2[2][2] = {};
            #pragma unroll
            for (int k = 0; k < HID; k++) {
                float2 xv = *(const float2*)&s1[k * PADA + a0];
                ulonglong2 wv = *(const ulonglong2*)&WbN[k * HID + o0];
                unsigned long long x0 = pack2(xv.x), x1 = pack2(xv.y);
                ffma2(acc2[0][0], x0, wv.x);
                ffma2(acc2[0][1], x0, wv.y);
                ffma2(acc2[1][0], x1, wv.x);
                ffma2(acc2[1][1], x1, wv.y);
            }
            #pragma unroll
            for (int p = 0; p < 2; p++) {
                part[2 * p]     += silu_f(lo32(acc2[0][p]) * 0.125f)
                                 + silu_f(lo32(acc2[1][p]) * 0.125f);
                part[2 * p + 1] += silu_f(hi32(acc2[0][p]) * 0.125f)
                                 + silu_f(hi32(acc2[1][p]) * 0.125f);
            }
            __syncthreads();   // s1/xs reused next tile
        }
    }

    // ===== reduce part[] over the 16 atom-groups (warp bits 0-3) =====
    #pragma unroll
    for (int off = 1; off < 16; off <<= 1)
        #pragma unroll
        for (int j = 0; j < 4; j++)
            part[j] += __shfl_xor_sync(0xffffffffu, part[j], off);

    float* red = xs;           // alias: xs dead now
    __syncthreads();
    if ((t & 15) == 0) {
        #pragma unroll
        for (int j = 0; j < 4; j++) red[o0 + j] = part[j];
    }
    __syncthreads();

    // ===== partial out: atomicAdd (red @ Wout[cls]) / 8 =====
    if (t < NOUT) {
        const float* wp = Wo + (size_t)cls * HID * NOUT + t;
        float s = 0.0f;
        #pragma unroll
        for (int h = 0; h < HID; h++)
            s += red[h] * __ldg(&wp[h * NOUT]);
        atomicAdd(&out[b * (NCLS * NOUT) + cls * NOUT + t], 0.125f * s);
    }
}

// ---------------------------------------------------------------------------
extern "C" void kernel_launch(void* const* d_in, const int* in_sizes, int n_in,
                              void* d_out, int out_size) {
    const float* af      = (const float*)d_in[0];   // atom_features
    const float* W0      = (const float*)d_in[1];   // W0_0
    const float* W1      = (const float*)d_in[5];   // W1_0
    const float* Wo      = (const float*)d_in[9];   // Wout
    const int*   mapping = (const int*)  d_in[10];  // mlp_mapping
    float* out = (float*)d_out;

    classify_kernel<<<NATOMS / 128, 128>>>(mapping, out);
    mlp_kernel<<<NBINS * 2, NT>>>(af, W0, W1, Wo, out);
}